// round 15
// baseline (speedup 1.0000x reference)
#include <cuda_runtime.h>
#include <cuda_bf16.h>
#include <cstdint>
#include <cstddef>

#define T_TOK 4096
#define HDIM  1024
#define IDIM  512
#define NEXP  16
#define MAXTILES 48

// stage image: [Ah|Al|Bh|Bl], each quadrant 128 rows x 32 k bf16, 80 B row stride
#define QUAD   10240
#define OFF_AL 10240
#define OFF_BH 20480
#define OFF_BL 30720
#define STAGE  40960
#define BLK    20480            // one packed hi|lo pair (A or B) per stage
#define SMEMSZ (2 * STAGE + 16)

// packed tile images (static device globals — no allocations)
__device__ __align__(256) unsigned char g_xp[(size_t)MAXTILES * 32 * BLK];      // x:  [tile][stage][hi|lo]
__device__ __align__(256) unsigned char g_wg[(size_t)NEXP * 8 * 32 * BLK];      // wgu:[e][by][stage][hi|lo]
__device__ __align__(256) unsigned char g_wd[(size_t)NEXP * 8 * 16 * BLK];      // wd: [e][by][stage][hi|lo]
__device__ __align__(256) unsigned char g_m2[(size_t)MAXTILES * 16 * BLK];      // mid:[tile][stage][hi|lo]
__device__ int g_te[MAXTILES], g_tr0[MAXTILES], g_trows[MAXTILES], g_nt;

__device__ __forceinline__ uint32_t smem_u32(const void* p) {
    uint32_t a;
    asm("{ .reg .u64 t; cvta.to.shared.u64 t, %1; cvt.u32.u64 %0, t; }" : "=r"(a) : "l"(p));
    return a;
}
__device__ __forceinline__ void bulkcp(uint32_t dst, const void* src, uint32_t bytes, uint32_t mb) {
    asm volatile("cp.async.bulk.shared::cluster.global.mbarrier::complete_tx::bytes [%0], [%1], %2, [%3];"
                 :: "r"(dst), "l"(src), "r"(bytes), "r"(mb) : "memory");
}
__device__ __forceinline__ void mbar_init(uint32_t a, uint32_t c) {
    asm volatile("mbarrier.init.shared.b64 [%0], %1;" :: "r"(a), "r"(c) : "memory");
}
__device__ __forceinline__ void mbar_expect(uint32_t a, uint32_t bytes) {
    asm volatile("mbarrier.arrive.expect_tx.shared.b64 _, [%0], %1;" :: "r"(a), "r"(bytes) : "memory");
}
__device__ __forceinline__ void mbar_wait(uint32_t a, uint32_t ph) {
    asm volatile(
        "{\n\t.reg .pred P1;\n\t"
        "W%=:\n\t"
        "mbarrier.try_wait.parity.acquire.cta.shared::cta.b64 P1, [%0], %1, 0x989680;\n\t"
        "@P1 bra.uni D%=;\n\t"
        "bra.uni W%=;\n\t"
        "D%=:\n\t}" :: "r"(a), "r"(ph) : "memory");
}
__device__ __forceinline__ void ldsm4(uint32_t* r, uint32_t a) {
    asm volatile("ldmatrix.sync.aligned.m8n8.x4.shared.b16 {%0,%1,%2,%3}, [%4];"
                 : "=r"(r[0]), "=r"(r[1]), "=r"(r[2]), "=r"(r[3]) : "r"(a));
}
__device__ __forceinline__ void mma16816(float* c, const uint32_t* a, const uint32_t* b) {
    asm volatile(
        "mma.sync.aligned.m16n8k16.row.col.f32.bf16.bf16.f32 "
        "{%0,%1,%2,%3}, {%4,%5,%6,%7}, {%8,%9}, {%0,%1,%2,%3};"
        : "+f"(c[0]), "+f"(c[1]), "+f"(c[2]), "+f"(c[3])
        : "r"(a[0]), "r"(a[1]), "r"(a[2]), "r"(a[3]), "r"(b[0]), "r"(b[1]));
}
__device__ __forceinline__ void split(float v, __nv_bfloat16& h, __nv_bfloat16& l) {
    h = __float2bfloat16_rn(v);
    l = __float2bfloat16_rn(v - __bfloat162float(h));
}

// warp-parallel worklist build: one lane per expert + shfl exclusive scans
__global__ void build_wl(const int* __restrict__ cnt) {
    int lane = threadIdx.x;
    int c  = (lane < NEXP) ? cnt[lane] : 0;
    int nt = (c + 127) >> 7;
    int incR = c, incT = nt;
    #pragma unroll
    for (int off = 1; off < 32; off <<= 1) {
        int vr = __shfl_up_sync(0xffffffffu, incR, off);
        int vt = __shfl_up_sync(0xffffffffu, incT, off);
        if (lane >= off) { incR += vr; incT += vt; }
    }
    int excR = incR - c, excT = incT - nt;
    if (lane < NEXP) {
        for (int i = 0; i < nt; i++) {
            int idx = excT + i;
            g_te[idx] = lane;
            g_tr0[idx] = excR + i * 128;
            int rem = c - i * 128;
            g_trows[idx] = rem < 128 ? rem : 128;
        }
        if (lane == NEXP - 1) g_nt = incT;
    }
}

// pack x (f32) -> per-(tile,stage) smem-image blocks, bf16 hi|lo (16B stores)
__global__ void prep_xp(const float* __restrict__ x) {
    int t = blockIdx.x;
    if (t >= g_nt) return;
    int s = blockIdx.y, row0 = g_tr0[t];
    int tid = threadIdx.x, r = tid >> 1, half = tid & 1;
    int gr = row0 + r; if (gr >= T_TOK) gr = T_TOK - 1;
    const float4* src = (const float4*)(x + (size_t)gr * HDIM + s * 32 + half * 16);
    unsigned char* dst = g_xp + (size_t)(t * 32 + s) * BLK + r * 80 + half * 32;
    uint32_t vh[8], vl[8];
    #pragma unroll
    for (int q = 0; q < 4; q++) {
        float4 f = src[q];
        __nv_bfloat16 h0, l0, h1, l1, h2, l2, h3, l3;
        split(f.x, h0, l0); split(f.y, h1, l1); split(f.z, h2, l2); split(f.w, h3, l3);
        __nv_bfloat162 ph0, ph1, pl0, pl1;
        ph0.x = h0; ph0.y = h1; ph1.x = h2; ph1.y = h3;
        pl0.x = l0; pl0.y = l1; pl1.x = l2; pl1.y = l3;
        vh[q*2] = *(uint32_t*)&ph0; vh[q*2+1] = *(uint32_t*)&ph1;
        vl[q*2] = *(uint32_t*)&pl0; vl[q*2+1] = *(uint32_t*)&pl1;
    }
    *(uint4*)dst               = *(uint4*)&vh[0];
    *(uint4*)(dst + 16)        = *(uint4*)&vh[4];
    *(uint4*)(dst + QUAD)      = *(uint4*)&vl[0];
    *(uint4*)(dst + QUAD + 16) = *(uint4*)&vl[4];
}

// pack weights (f32, n-contiguous) -> per-(e,by,stage) K-major smem-image blocks.
// W=0: gate_up [1024 k][1024 n] with gate/up interleave; W=1: down [512 k][1024 n].
// Each thread owns 4 consecutive k of one n-column -> two 8B stores (64B runs/warp).
template<int RD, int CD, int W>
__global__ void prep_w(const float* __restrict__ in) {
    __shared__ float tb[32][33];
    int e = blockIdx.z;
    const float* I = in + (size_t)e * RD * CD;
    int c0 = blockIdx.x * 32, r0 = blockIdx.y * 32;
    int tid = threadIdx.x;
    int tx = tid & 31, ty = tid >> 5;
    #pragma unroll
    for (int j = 0; j < 32; j += 8)
        tb[ty + j][tx] = I[(size_t)(r0 + ty + j) * CD + c0 + tx];
    __syncthreads();
    int cl = tid >> 3, quad = tid & 7;
    int col = c0 + cl;
    uint32_t ph[2], pl[2];
    #pragma unroll
    for (int i = 0; i < 2; i++) {
        __nv_bfloat16 h0, l0, h1, l1;
        split(tb[quad * 4 + 2 * i][cl],     h0, l0);
        split(tb[quad * 4 + 2 * i + 1][cl], h1, l1);
        __nv_bfloat162 hh, ll;
        hh.x = h0; hh.y = h1; ll.x = l0; ll.y = l1;
        ph[i] = *(uint32_t*)&hh; pl[i] = *(uint32_t*)&ll;
    }
    int by, r;
    if (W == 0) {
        int up = (col >= IDIM) ? 1 : 0;
        int o = up ? (col - IDIM) : col;
        by = o >> 6; int oo = o & 63;
        r = (oo >> 4) * 32 + up * 16 + ((oo >> 3) & 1) * 8 + (oo & 7);
    } else { by = col >> 7; r = col & 127; }
    int s = r0 >> 5;
    size_t blk = W ? (size_t)((e * 8 + by) * 16 + s) : (size_t)((e * 8 + by) * 32 + s);
    unsigned char* p = (W ? g_wd : g_wg) + blk * BLK + r * 80 + quad * 8;
    *(uint2*)p          = *(uint2*)ph;
    *(uint2*)(p + QUAD) = *(uint2*)pl;
}

// G=1: x@wgu + SwiGLU -> packed mid.  G=2: mid@wd -> out (f32).
// 128x128 CTA tile; 2-stage mbarrier pipeline fed by cp.async.bulk.
template<int G>
__global__ void __launch_bounds__(256, 2) gemm(float* __restrict__ out) {
    extern __shared__ char sm[];
    uint32_t sb = smem_u32(sm);
    int t = blockIdx.x;
    if (t >= g_nt) return;
    int e = g_te[t], row0 = g_tr0[t], rows = g_trows[t];
    int by = blockIdx.y;
    int tid = threadIdx.x, wid = tid >> 5, lane = tid & 31;
    int wm = wid >> 2, wn = wid & 3;
    const int NS = (G == 1) ? 32 : 16;

    const unsigned char* srcA = (G == 1) ? g_xp + (size_t)(t * 32) * BLK
                                         : g_m2 + (size_t)(t * 16) * BLK;
    const unsigned char* srcB = (G == 1) ? g_wg + (size_t)((e * 8 + by) * 32) * BLK
                                         : g_wd + (size_t)((e * 8 + by) * 16) * BLK;
    uint32_t mb = sb + 2 * STAGE;
    if (tid == 0) { mbar_init(mb, 1); mbar_init(mb + 8, 1); }
    __syncthreads();

    auto issue = [&](int s) {
        if (tid == 0) {
            uint32_t m = mb + (s & 1) * 8;
            uint32_t so = sb + (uint32_t)(s & 1) * STAGE;
            mbar_expect(m, STAGE);
            bulkcp(so,          srcA + (size_t)s * BLK, BLK, m);
            bulkcp(so + OFF_BH, srcB + (size_t)s * BLK, BLK, m);
        }
    };
    issue(0); issue(1);

    float acc[4][4][4] = {};
    uint32_t aRowB = (uint32_t)((wm * 64 + (lane & 15)) * 80 + (lane >> 4) * 16);
    uint32_t bRowB = (uint32_t)((wn * 32 + (lane >> 4) * 8 + (lane & 7)) * 80 + ((lane >> 3) & 1) * 16);

    for (int s = 0; s < NS; s++) {
        mbar_wait(mb + (s & 1) * 8, (s >> 1) & 1);
        uint32_t so = sb + (uint32_t)(s & 1) * STAGE;
        #pragma unroll
        for (int ks = 0; ks < 2; ks++) {
            uint32_t bh[4][2], bl[4][2];
            #pragma unroll
            for (int p = 0; p < 2; p++) {
                uint32_t b = so + OFF_BH + bRowB + p * 1280 + ks * 32;
                uint32_t r4[4];
                ldsm4(r4, b);
                bh[2*p][0] = r4[0]; bh[2*p][1] = r4[1];
                bh[2*p+1][0] = r4[2]; bh[2*p+1][1] = r4[3];
                ldsm4(r4, b + QUAD);
                bl[2*p][0] = r4[0]; bl[2*p][1] = r4[1];
                bl[2*p+1][0] = r4[2]; bl[2*p+1][1] = r4[3];
            }
            #pragma unroll
            for (int fm = 0; fm < 4; fm++) {
                uint32_t ah[4], al[4];
                uint32_t a = so + aRowB + fm * 1280 + ks * 32;
                ldsm4(ah, a);
                ldsm4(al, a + OFF_AL);
                #pragma unroll
                for (int fn = 0; fn < 4; fn++) {
                    mma16816(acc[fm][fn], ah, bh[fn]);   // hi*hi
                    mma16816(acc[fm][fn], ah, bl[fn]);   // hi*lo
                    mma16816(acc[fm][fn], al, bh[fn]);   // lo*hi
                }
            }
        }
        __syncthreads();
        if (s + 2 < NS) issue(s + 2);
    }

    if (G == 1) {
        // fn={0,1}: gate cols; fn={2,3}: matching up cols -> fused SwiGLU -> packed mid
        int s2 = by * 2 + (wn >> 1);
        #pragma unroll
        for (int fm = 0; fm < 4; fm++)
            #pragma unroll
            for (int half = 0; half < 2; half++) {
                int lr = wm * 64 + fm * 16 + (lane >> 2) + half * 8;
                if (lr < rows) {
                    #pragma unroll
                    for (int f = 0; f < 2; f++) {
                        float g0 = acc[fm][f][half*2],   g1 = acc[fm][f][half*2+1];
                        float u0 = acc[fm][f+2][half*2], u1 = acc[fm][f+2][half*2+1];
                        float v0 = u0 * g0 / (1.f + __expf(-g0));
                        float v1 = u1 * g1 / (1.f + __expf(-g1));
                        __nv_bfloat16 h0, l0, h1, l1;
                        split(v0, h0, l0); split(v1, h1, l1);
                        __nv_bfloat162 hv, lv;
                        hv.x = h0; hv.y = h1; lv.x = l0; lv.y = l1;
                        int kin = (wn & 1) * 16 + (lane & 3) * 2 + f * 8;
                        unsigned char* p = g_m2 + (size_t)(t * 16 + s2) * BLK + lr * 80 + kin * 2;
                        *(__nv_bfloat162*)p = hv;
                        *(__nv_bfloat162*)(p + QUAD) = lv;
                    }
                }
            }
    } else {
        int cb = by * 128;
        #pragma unroll
        for (int fm = 0; fm < 4; fm++)
            #pragma unroll
            for (int half = 0; half < 2; half++) {
                int lr = wm * 64 + fm * 16 + (lane >> 2) + half * 8;
                if (lr < rows) {
                    float* op = out + (size_t)(row0 + lr) * HDIM + cb + wn * 32 + (lane & 3) * 2;
                    #pragma unroll
                    for (int fn = 0; fn < 4; fn++) {
                        float2 v;
                        v.x = acc[fm][fn][half*2];
                        v.y = acc[fm][fn][half*2+1];
                        *(float2*)(op + fn * 8) = v;
                    }
                }
            }
    }
}

extern "C" void kernel_launch(void* const* d_in, const int* in_sizes, int n_in,
                              void* d_out, int out_size) {
    const float* x   = (const float*)d_in[0];
    const float* wgu = (const float*)d_in[1];
    const float* wd  = (const float*)d_in[2];
    const int*   cnt = (const int*)d_in[3];
    float* out = (float*)d_out;

    cudaFuncSetAttribute(gemm<1>, cudaFuncAttributeMaxDynamicSharedMemorySize, SMEMSZ);
    cudaFuncSetAttribute(gemm<2>, cudaFuncAttributeMaxDynamicSharedMemorySize, SMEMSZ);

    build_wl<<<1, 32>>>(cnt);
    prep_xp<<<dim3(MAXTILES, 32), 256>>>(x);
    prep_w<HDIM, 2 * IDIM, 0><<<dim3(32, HDIM / 32, NEXP), 256>>>(wgu);
    prep_w<IDIM, HDIM, 1><<<dim3(32, IDIM / 32, NEXP), 256>>>(wd);
    gemm<1><<<dim3(MAXTILES, 8), 256, SMEMSZ>>>(out);
    gemm<2><<<dim3(MAXTILES, 8), 256, SMEMSZ>>>(out);
}

// round 16
// speedup vs baseline: 1.9168x; 1.9168x over previous
#include <cuda_runtime.h>
#include <cuda_fp16.h>
#include <cstdint>
#include <cstddef>

#define T_TOK 4096
#define HDIM  1024
#define IDIM  512
#define NEXP  16
#define MAXTILES 48

// stage image: [A|B], each 128 rows x 32 k fp16, 80 B row stride (16B pad -> conflict-free ldsm)
#define BLK    10240            // one packed fp16 image (A or B) per stage
#define OFF_B  10240
#define STAGE  20480
#define NSTG   4
#define SMEMSZ (NSTG * STAGE + 64)

// packed tile images (static device globals — no allocations)
__device__ __align__(256) unsigned char g_xp[(size_t)MAXTILES * 32 * BLK];   // x:  [tile][stage]
__device__ __align__(256) unsigned char g_wg[(size_t)NEXP * 8 * 32 * BLK];   // wgu:[e][by][stage]
__device__ __align__(256) unsigned char g_wd[(size_t)NEXP * 8 * 16 * BLK];   // wd: [e][by][stage]
__device__ __align__(256) unsigned char g_m2[(size_t)MAXTILES * 16 * BLK];   // mid:[tile][stage]
__device__ int g_te[MAXTILES], g_tr0[MAXTILES], g_trows[MAXTILES], g_nt;

__device__ __forceinline__ uint32_t smem_u32(const void* p) {
    uint32_t a;
    asm("{ .reg .u64 t; cvta.to.shared.u64 t, %1; cvt.u32.u64 %0, t; }" : "=r"(a) : "l"(p));
    return a;
}
__device__ __forceinline__ void bulkcp(uint32_t dst, const void* src, uint32_t bytes, uint32_t mb) {
    asm volatile("cp.async.bulk.shared::cluster.global.mbarrier::complete_tx::bytes [%0], [%1], %2, [%3];"
                 :: "r"(dst), "l"(src), "r"(bytes), "r"(mb) : "memory");
}
__device__ __forceinline__ void mbar_init(uint32_t a, uint32_t c) {
    asm volatile("mbarrier.init.shared.b64 [%0], %1;" :: "r"(a), "r"(c) : "memory");
}
__device__ __forceinline__ void mbar_expect(uint32_t a, uint32_t bytes) {
    asm volatile("mbarrier.arrive.expect_tx.shared.b64 _, [%0], %1;" :: "r"(a), "r"(bytes) : "memory");
}
__device__ __forceinline__ void mbar_wait(uint32_t a, uint32_t ph) {
    asm volatile(
        "{\n\t.reg .pred P1;\n\t"
        "W%=:\n\t"
        "mbarrier.try_wait.parity.acquire.cta.shared::cta.b64 P1, [%0], %1, 0x989680;\n\t"
        "@P1 bra.uni D%=;\n\t"
        "bra.uni W%=;\n\t"
        "D%=:\n\t}" :: "r"(a), "r"(ph) : "memory");
}
__device__ __forceinline__ void ldsm4(uint32_t* r, uint32_t a) {
    asm volatile("ldmatrix.sync.aligned.m8n8.x4.shared.b16 {%0,%1,%2,%3}, [%4];"
                 : "=r"(r[0]), "=r"(r[1]), "=r"(r[2]), "=r"(r[3]) : "r"(a));
}
__device__ __forceinline__ void mma16816(float* c, const uint32_t* a, const uint32_t* b) {
    asm volatile(
        "mma.sync.aligned.m16n8k16.row.col.f32.f16.f16.f32 "
        "{%0,%1,%2,%3}, {%4,%5,%6,%7}, {%8,%9}, {%0,%1,%2,%3};"
        : "+f"(c[0]), "+f"(c[1]), "+f"(c[2]), "+f"(c[3])
        : "r"(a[0]), "r"(a[1]), "r"(a[2]), "r"(a[3]), "r"(b[0]), "r"(b[1]));
}

// warp-parallel worklist build: one lane per expert + shfl exclusive scans
__global__ void build_wl(const int* __restrict__ cnt) {
    int lane = threadIdx.x;
    int c  = (lane < NEXP) ? cnt[lane] : 0;
    int nt = (c + 127) >> 7;
    int incR = c, incT = nt;
    #pragma unroll
    for (int off = 1; off < 32; off <<= 1) {
        int vr = __shfl_up_sync(0xffffffffu, incR, off);
        int vt = __shfl_up_sync(0xffffffffu, incT, off);
        if (lane >= off) { incR += vr; incT += vt; }
    }
    int excR = incR - c, excT = incT - nt;
    if (lane < NEXP) {
        for (int i = 0; i < nt; i++) {
            int idx = excT + i;
            g_te[idx] = lane;
            g_tr0[idx] = excR + i * 128;
            int rem = c - i * 128;
            g_trows[idx] = rem < 128 ? rem : 128;
        }
        if (lane == NEXP - 1) g_nt = incT;
    }
}

// pack x (f32) -> per-(tile,stage) fp16 smem-image blocks
__global__ void prep_xp(const float* __restrict__ x) {
    int t = blockIdx.x;
    if (t >= g_nt) return;
    int s = blockIdx.y, row0 = g_tr0[t];
    int tid = threadIdx.x, r = tid >> 1, half = tid & 1;
    int gr = row0 + r; if (gr >= T_TOK) gr = T_TOK - 1;
    const float4* src = (const float4*)(x + (size_t)gr * HDIM + s * 32 + half * 16);
    unsigned char* dst = g_xp + (size_t)(t * 32 + s) * BLK + r * 80 + half * 32;
    uint32_t v[8];
    #pragma unroll
    for (int q = 0; q < 4; q++) {
        float4 f = src[q];
        __half2 p0 = __floats2half2_rn(f.x, f.y);
        __half2 p1 = __floats2half2_rn(f.z, f.w);
        v[q*2] = *(uint32_t*)&p0; v[q*2+1] = *(uint32_t*)&p1;
    }
    *(uint4*)dst        = *(uint4*)&v[0];
    *(uint4*)(dst + 16) = *(uint4*)&v[4];
}

// pack weights (f32, n-contiguous [k][n]) -> per-(e,by,stage) K-major fp16 images.
// W=0: gate_up (gate/up interleave); W=1: down (plain).  Tile: 32 k x 64 n.
template<int RD, int CD, int W>
__global__ void prep_w(const float* __restrict__ in) {
    __shared__ float tb[32][65];
    int e = blockIdx.z;
    const float* I = in + (size_t)e * RD * CD;
    int c0 = blockIdx.x * 64, r0 = blockIdx.y * 32;
    int tid = threadIdx.x;
    #pragma unroll
    for (int i = 0; i < 2; i++) {
        int idx = tid + i * 256, row = idx >> 4, c4 = idx & 15;
        float4 f = *(const float4*)(I + (size_t)(r0 + row) * CD + c0 + c4 * 4);
        tb[row][c4*4+0] = f.x; tb[row][c4*4+1] = f.y;
        tb[row][c4*4+2] = f.z; tb[row][c4*4+3] = f.w;
    }
    __syncthreads();
    int cl = tid >> 2, oct = tid & 3;                   // 64 cols x 4 k-octs
    int col = c0 + cl;
    uint32_t v[4];
    #pragma unroll
    for (int i = 0; i < 4; i++) {
        __half2 p = __floats2half2_rn(tb[oct*8 + 2*i][cl], tb[oct*8 + 2*i + 1][cl]);
        v[i] = *(uint32_t*)&p;
    }
    int by, r;
    if (W == 0) {
        int up = (col >= IDIM) ? 1 : 0;
        int o = up ? (col - IDIM) : col;
        by = o >> 6; int oo = o & 63;
        r = (oo >> 4) * 32 + up * 16 + ((oo >> 3) & 1) * 8 + (oo & 7);
    } else { by = col >> 7; r = col & 127; }
    int s = r0 >> 5;
    size_t blk = W ? (size_t)((e * 8 + by) * 16 + s) : (size_t)((e * 8 + by) * 32 + s);
    unsigned char* p = (W ? g_wd : g_wg) + blk * BLK + r * 80 + oct * 16;
    *(uint4*)p = *(uint4*)v;
}

// G=1: x@wgu + SwiGLU -> packed mid (fp16).  G=2: mid@wd -> out (f32).
// 128x128 CTA tile; 4-stage mbarrier ring fed by cp.async.bulk; single-pass fp16 MMA.
template<int G>
__global__ void __launch_bounds__(256, 2) gemm(float* __restrict__ out) {
    extern __shared__ char sm[];
    uint32_t sb = smem_u32(sm);
    int t = blockIdx.x;
    if (t >= g_nt) return;
    int e = g_te[t], row0 = g_tr0[t], rows = g_trows[t];
    int by = blockIdx.y;
    int tid = threadIdx.x, wid = tid >> 5, lane = tid & 31;
    int wm = wid >> 2, wn = wid & 3;
    const int NS = (G == 1) ? 32 : 16;

    const unsigned char* srcA = (G == 1) ? g_xp + (size_t)(t * 32) * BLK
                                         : g_m2 + (size_t)(t * 16) * BLK;
    const unsigned char* srcB = (G == 1) ? g_wg + (size_t)((e * 8 + by) * 32) * BLK
                                         : g_wd + (size_t)((e * 8 + by) * 16) * BLK;
    uint32_t mb = sb + NSTG * STAGE;
    if (tid == 0)
        #pragma unroll
        for (int i = 0; i < NSTG; i++) mbar_init(mb + i * 8, 1);
    __syncthreads();

    auto issue = [&](int s) {
        if (tid == 0) {
            uint32_t m = mb + (s & (NSTG - 1)) * 8;
            uint32_t so = sb + (uint32_t)(s & (NSTG - 1)) * STAGE;
            mbar_expect(m, STAGE);
            bulkcp(so,         srcA + (size_t)s * BLK, BLK, m);
            bulkcp(so + OFF_B, srcB + (size_t)s * BLK, BLK, m);
        }
    };
    #pragma unroll
    for (int i = 0; i < NSTG; i++) if (i < NS) issue(i);

    float acc[4][4][4] = {};
    uint32_t aRowB = (uint32_t)((wm * 64 + (lane & 15)) * 80 + (lane >> 4) * 16);
    uint32_t bRowB = (uint32_t)((wn * 32 + (lane >> 4) * 8 + (lane & 7)) * 80 + ((lane >> 3) & 1) * 16);

    for (int s = 0; s < NS; s++) {
        mbar_wait(mb + (s & (NSTG - 1)) * 8, (s >> 2) & 1);
        uint32_t so = sb + (uint32_t)(s & (NSTG - 1)) * STAGE;
        #pragma unroll
        for (int ks = 0; ks < 2; ks++) {
            uint32_t bf[4][2];
            #pragma unroll
            for (int p = 0; p < 2; p++) {
                uint32_t r4[4];
                ldsm4(r4, so + OFF_B + bRowB + p * 1280 + ks * 32);
                bf[2*p][0] = r4[0]; bf[2*p][1] = r4[1];
                bf[2*p+1][0] = r4[2]; bf[2*p+1][1] = r4[3];
            }
            #pragma unroll
            for (int fm = 0; fm < 4; fm++) {
                uint32_t af[4];
                ldsm4(af, so + aRowB + fm * 1280 + ks * 32);
                #pragma unroll
                for (int fn = 0; fn < 4; fn++)
                    mma16816(acc[fm][fn], af, bf[fn]);
            }
        }
        __syncthreads();
        if (s + NSTG < NS) issue(s + NSTG);
    }

    if (G == 1) {
        // fn={0,1}: gate cols; fn={2,3}: matching up cols -> fused SwiGLU -> packed fp16 mid
        int s2 = by * 2 + (wn >> 1);
        #pragma unroll
        for (int fm = 0; fm < 4; fm++)
            #pragma unroll
            for (int half = 0; half < 2; half++) {
                int lr = wm * 64 + fm * 16 + (lane >> 2) + half * 8;
                if (lr < rows) {
                    #pragma unroll
                    for (int f = 0; f < 2; f++) {
                        float g0 = acc[fm][f][half*2],   g1 = acc[fm][f][half*2+1];
                        float u0 = acc[fm][f+2][half*2], u1 = acc[fm][f+2][half*2+1];
                        float v0 = u0 * g0 / (1.f + __expf(-g0));
                        float v1 = u1 * g1 / (1.f + __expf(-g1));
                        __half2 hv = __floats2half2_rn(v0, v1);
                        int kin = (wn & 1) * 16 + (lane & 3) * 2 + f * 8;
                        *(__half2*)(g_m2 + (size_t)(t * 16 + s2) * BLK + lr * 80 + kin * 2) = hv;
                    }
                }
            }
    } else {
        int cb = by * 128;
        #pragma unroll
        for (int fm = 0; fm < 4; fm++)
            #pragma unroll
            for (int half = 0; half < 2; half++) {
                int lr = wm * 64 + fm * 16 + (lane >> 2) + half * 8;
                if (lr < rows) {
                    float* op = out + (size_t)(row0 + lr) * HDIM + cb + wn * 32 + (lane & 3) * 2;
                    #pragma unroll
                    for (int fn = 0; fn < 4; fn++) {
                        float2 v;
                        v.x = acc[fm][fn][half*2];
                        v.y = acc[fm][fn][half*2+1];
                        *(float2*)(op + fn * 8) = v;
                    }
                }
            }
    }
}

extern "C" void kernel_launch(void* const* d_in, const int* in_sizes, int n_in,
                              void* d_out, int out_size) {
    const float* x   = (const float*)d_in[0];
    const float* wgu = (const float*)d_in[1];
    const float* wd  = (const float*)d_in[2];
    const int*   cnt = (const int*)d_in[3];
    float* out = (float*)d_out;

    cudaFuncSetAttribute(gemm<1>, cudaFuncAttributeMaxDynamicSharedMemorySize, SMEMSZ);
    cudaFuncSetAttribute(gemm<2>, cudaFuncAttributeMaxDynamicSharedMemorySize, SMEMSZ);

    build_wl<<<1, 32>>>(cnt);
    prep_xp<<<dim3(MAXTILES, 32), 256>>>(x);
    prep_w<HDIM, 2 * IDIM, 0><<<dim3(2 * IDIM / 64, HDIM / 32, NEXP), 256>>>(wgu);
    prep_w<IDIM, HDIM, 1><<<dim3(HDIM / 64, IDIM / 32, NEXP), 256>>>(wd);
    gemm<1><<<dim3(MAXTILES, 8), 256, SMEMSZ>>>(out);
    gemm<2><<<dim3(MAXTILES, 8), 256, SMEMSZ>>>(out);
}